// round 2
// baseline (speedup 1.0000x reference)
#include <cuda_runtime.h>
#include <cstdint>

// Problem constants
#define NROWS   4096
#define INFEAT  4096
#define OUTFEAT 4096
#define NCODE   256      // C codebooks
#define KLEAF   16
// Aggregation tiling
#define TO      128      // outputs per block
#define TN      128      // rows per block
#define CCH     8        // codebooks per SMEM chunk
#define NCHUNK  (NCODE / CCH)        // 32
#define CHFLOAT (CCH * KLEAF)        // 128 floats per output row per chunk
#define AGG_SMEM (CHFLOAT * TO * 4)  // 64 KB

// Static device scratch for codes (aligned for uint2 loads)
__device__ __align__(16) unsigned char g_codes[NROWS * NCODE];

// ---------------------------------------------------------------------------
// Kernel 1: encode. One block per row, one thread per codebook.
// Heap walk: node i (1-based), compare x_d vs thr[c*15 + (i-1)], right iff >.
// Leaf code = i - 16.
// ---------------------------------------------------------------------------
__global__ void __launch_bounds__(NCODE) encode_kernel(
    const float* __restrict__ input,
    const int*   __restrict__ dims,
    const float* __restrict__ thr)
{
    const int n = blockIdx.x;
    const int c = threadIdx.x;

    const int4 d4 = *reinterpret_cast<const int4*>(dims + c * 4);
    const float* row = input + (size_t)n * INFEAT;
    const float x0 = __ldg(row + d4.x);
    const float x1 = __ldg(row + d4.y);
    const float x2 = __ldg(row + d4.z);
    const float x3 = __ldg(row + d4.w);

    const float* t = thr + c * 15;
    int i = 1;
    i = 2 * i + (x0 > __ldg(t + i - 1) ? 1 : 0);
    i = 2 * i + (x1 > __ldg(t + i - 1) ? 1 : 0);
    i = 2 * i + (x2 > __ldg(t + i - 1) ? 1 : 0);
    i = 2 * i + (x3 > __ldg(t + i - 1) ? 1 : 0);

    g_codes[n * NCODE + c] = (unsigned char)(i - 16);
}

// ---------------------------------------------------------------------------
// Kernel 2: LUT aggregation.
// Block: 256 threads (8 warps). Tile: TO=128 outputs x TN=128 rows.
// SMEM layout (transposed): lut_t[idx][op], idx = cc*16+code in [0,128),
// op in [0,128), stride 128 floats.
//   - Staging: thread owns op = tid&127 -> transposed scalar STS are
//     conflict-free (consecutive lanes -> consecutive banks); global LDG.128.
//   - Gather: code byte is warp-uniform -> LDS.128 at idx*128 + lane*4 is
//     conflict-free; one LDS.128 covers the lane's 4 consecutive outputs.
// Each warp owns 16 consecutive rows; acc[16][4] in registers.
// ---------------------------------------------------------------------------
__global__ void __launch_bounds__(256, 2) agg_kernel(
    const float* __restrict__ lut,
    float* __restrict__ out)
{
    extern __shared__ float lut_t[];   // [CHFLOAT][TO] = [128][128]

    const int o0   = blockIdx.x * TO;
    const int n0   = blockIdx.y * TN;
    const int tid  = threadIdx.x;
    const int warp = tid >> 5;
    const int lane = tid & 31;
    const int rowbase = n0 + warp * 16;

    const int op   = tid & 127;        // staging: owned output column
    const int half = tid >> 7;         // staging: which half of the 32 float4s

    float acc[16][4];
#pragma unroll
    for (int t = 0; t < 16; ++t)
#pragma unroll
        for (int j = 0; j < 4; ++j) acc[t][j] = 0.0f;

    for (int ch = 0; ch < NCHUNK; ++ch) {
        const int c0 = ch * CCH;
        __syncthreads();   // previous chunk's readers done before overwrite

        // Stage: 128 output rows x 128 floats, transposed into lut_t
        const float* gsrc = lut + (size_t)(o0 + op) * (NCODE * KLEAF) + c0 * KLEAF;
#pragma unroll
        for (int i = 0; i < 16; ++i) {
            const int w = half * 16 + i;               // float4 index 0..31
            const float4 v = *reinterpret_cast<const float4*>(gsrc + w * 4);
            lut_t[(w * 4 + 0) * TO + op] = v.x;
            lut_t[(w * 4 + 1) * TO + op] = v.y;
            lut_t[(w * 4 + 2) * TO + op] = v.z;
            lut_t[(w * 4 + 3) * TO + op] = v.w;
        }
        __syncthreads();

        // Gather-accumulate: warp-uniform idx, conflict-free LDS.128
#pragma unroll
        for (int t = 0; t < 16; ++t) {
            const int row = rowbase + t;
            const uint2 cw = *reinterpret_cast<const uint2*>(
                g_codes + row * NCODE + c0);           // warp-uniform broadcast
            const unsigned int lo = cw.x, hi = cw.y;
#pragma unroll
            for (int cc = 0; cc < 8; ++cc) {
                const unsigned int byte =
                    (cc < 4) ? ((lo >> (8 * cc)) & 0xFFu)
                             : ((hi >> (8 * (cc - 4))) & 0xFFu);
                const int idx = cc * KLEAF + (int)byte;
                const float4 v = *reinterpret_cast<const float4*>(
                    lut_t + idx * TO + lane * 4);
                acc[t][0] += v.x;
                acc[t][1] += v.y;
                acc[t][2] += v.z;
                acc[t][3] += v.w;
            }
        }
    }

    // Write results: lane's 4 outputs are consecutive -> STG.128 coalesced
#pragma unroll
    for (int t = 0; t < 16; ++t) {
        float4 r;
        r.x = acc[t][0]; r.y = acc[t][1]; r.z = acc[t][2]; r.w = acc[t][3];
        *reinterpret_cast<float4*>(
            out + (size_t)(rowbase + t) * OUTFEAT + o0 + lane * 4) = r;
    }
}

// ---------------------------------------------------------------------------
// Launch. Inputs (metadata order): inputMatrix f32[4096*4096], dims i32[1024],
// selection_matrix (unused), thresholds f32[3840], tree_des_mat (unused),
// lut f32[4096*256*16]. Output f32[4096*4096].
// ---------------------------------------------------------------------------
extern "C" void kernel_launch(void* const* d_in, const int* in_sizes, int n_in,
                              void* d_out, int out_size)
{
    const float* input = (const float*)d_in[0];
    const int*   dims  = (const int*)  d_in[1];
    const float* thr   = (const float*)d_in[3];
    const float* lut   = (const float*)d_in[5];
    float*       out   = (float*)d_out;

    (void)in_sizes; (void)n_in; (void)out_size;

    cudaFuncSetAttribute(agg_kernel,
                         cudaFuncAttributeMaxDynamicSharedMemorySize, AGG_SMEM);

    encode_kernel<<<NROWS, NCODE>>>(input, dims, thr);

    dim3 grid(OUTFEAT / TO, NROWS / TN);
    agg_kernel<<<grid, 256, AGG_SMEM>>>(lut, out);
}

// round 3
// speedup vs baseline: 1.9963x; 1.9963x over previous
#include <cuda_runtime.h>
#include <cuda_fp16.h>
#include <cstdint>

// Problem constants
#define NROWS   4096
#define INFEAT  4096
#define OUTFEAT 4096
#define NCODE   256      // C codebooks
#define KLEAF   16
#define KGLOB   (NCODE * KLEAF)   // 4096
// Aggregation tiling
#define TO      128      // outputs per block
#define TN      128      // rows per block
#define CCH     8        // codebooks per SMEM chunk
#define NCHUNK  (NCODE / CCH)          // 32
#define CHIDX   (CCH * KLEAF)          // 128 idx rows per chunk
#define AGG_SMEM (CHIDX * TO * 2)      // 32 KB (half)

// Static device scratch
__device__ __align__(16) unsigned char g_codes[NROWS * NCODE];   // 1 MB
__device__ __align__(16) __half        g_lutT[KGLOB * OUTFEAT];  // 32 MB, [k][o]

// ---------------------------------------------------------------------------
// Kernel 1: encode. One block per row, one thread per codebook.
// ---------------------------------------------------------------------------
__global__ void __launch_bounds__(NCODE) encode_kernel(
    const float* __restrict__ input,
    const int*   __restrict__ dims,
    const float* __restrict__ thr)
{
    const int n = blockIdx.x;
    const int c = threadIdx.x;

    const int4 d4 = *reinterpret_cast<const int4*>(dims + c * 4);
    const float* row = input + (size_t)n * INFEAT;
    const float x0 = __ldg(row + d4.x);
    const float x1 = __ldg(row + d4.y);
    const float x2 = __ldg(row + d4.z);
    const float x3 = __ldg(row + d4.w);

    const float* t = thr + c * 15;
    int i = 1;
    i = 2 * i + (x0 > __ldg(t + i - 1) ? 1 : 0);
    i = 2 * i + (x1 > __ldg(t + i - 1) ? 1 : 0);
    i = 2 * i + (x2 > __ldg(t + i - 1) ? 1 : 0);
    i = 2 * i + (x3 > __ldg(t + i - 1) ? 1 : 0);

    g_codes[n * NCODE + c] = (unsigned char)(i - 16);
}

// ---------------------------------------------------------------------------
// Kernel 1b: transpose + fp32->fp16 convert of lut.
//   in : lut[o][k] fp32 (k = c*16+leaf, row stride 4096)
//   out: g_lutT[k][o] half
// 64x64 tiles via SMEM, 256 threads.
// ---------------------------------------------------------------------------
__global__ void __launch_bounds__(256) transpose_kernel(
    const float* __restrict__ lut)
{
    __shared__ __half tile[64][66];   // pad 66: stride 132B -> conflict-free

    const int k0 = blockIdx.x * 64;
    const int o0 = blockIdx.y * 64;
    const int tid = threadIdx.x;

#pragma unroll
    for (int j = 0; j < 16; ++j) {
        const int flat = j * 256 + tid;     // 0..4095
        const int o = flat >> 6;            // 0..63
        const int k = flat & 63;            // coalesced along k
        tile[k][o] = __float2half(
            __ldg(lut + (size_t)(o0 + o) * KGLOB + k0 + k));
    }
    __syncthreads();
#pragma unroll
    for (int j = 0; j < 16; ++j) {
        const int flat = j * 256 + tid;
        const int k = flat >> 6;
        const int o = flat & 63;            // coalesced along o
        g_lutT[(size_t)(k0 + k) * OUTFEAT + o0 + o] = tile[k][o];
    }
}

// ---------------------------------------------------------------------------
// Kernel 2: LUT aggregation (fp16 SMEM, LDS.32 gathers, fp32 accumulate).
// Block: 256 threads (8 warps). Tile: TO=128 outputs x TN=128 rows.
// SMEM: lut_s2[idx][64] half2 (idx = cc*16 + code in [0,128)), row = 256 B.
//   - Stage: flat uint4 copy of g_lutT[c0*16 .. +128)[o0 .. o0+128) -> fully
//     coalesced LDG.128 + contiguous STS.128 (no transpose needed).
//   - Gather: idx warp-uniform; lane reads half2 at idx*64+lane and
//     idx*64+32+lane -> each LDS.32 is a single 128B wavefront, conflict-free.
// Lane owns outputs {2*lane, 2*lane+1, 64+2*lane, 64+2*lane+1}.
// ---------------------------------------------------------------------------
__global__ void __launch_bounds__(256, 2) agg_kernel(float* __restrict__ out)
{
    extern __shared__ __half2 lut_s2[];    // [CHIDX][TO/2]

    const int o0   = blockIdx.x * TO;
    const int n0   = blockIdx.y * TN;
    const int tid  = threadIdx.x;
    const int warp = tid >> 5;
    const int lane = tid & 31;
    const int rowbase = n0 + warp * 16;

    float acc[16][4];
#pragma unroll
    for (int t = 0; t < 16; ++t)
#pragma unroll
        for (int j = 0; j < 4; ++j) acc[t][j] = 0.0f;

    for (int ch = 0; ch < NCHUNK; ++ch) {
        const int c0 = ch * CCH;
        __syncthreads();   // previous chunk's readers done before overwrite

        // Stage 128 idx-rows x 256 B = 32 KB (2048 uint4, 8 per thread)
#pragma unroll
        for (int i = 0; i < 8; ++i) {
            const int flat = i * 256 + tid;      // 0..2047
            const int idx  = flat >> 4;          // idx row 0..127
            const int pos  = flat & 15;          // uint4 within row
            const uint4 v = *reinterpret_cast<const uint4*>(
                g_lutT + (size_t)(c0 * KLEAF + idx) * OUTFEAT + o0 + pos * 8);
            reinterpret_cast<uint4*>(lut_s2)[flat] = v;
        }
        __syncthreads();

        // Gather-accumulate
#pragma unroll
        for (int t = 0; t < 16; ++t) {
            const int row = rowbase + t;
            const uint2 cw = *reinterpret_cast<const uint2*>(
                g_codes + row * NCODE + c0);     // warp-uniform broadcast
            const unsigned int lo = cw.x, hi = cw.y;
#pragma unroll
            for (int cc = 0; cc < 8; ++cc) {
                const unsigned int byte =
                    (cc < 4) ? ((lo >> (8 * cc)) & 0xFFu)
                             : ((hi >> (8 * (cc - 4))) & 0xFFu);
                const int idx = cc * KLEAF + (int)byte;
                const __half2 v0 = lut_s2[idx * (TO / 2) + lane];
                const __half2 v1 = lut_s2[idx * (TO / 2) + 32 + lane];
                const float2 f0 = __half22float2(v0);
                const float2 f1 = __half22float2(v1);
                acc[t][0] += f0.x;
                acc[t][1] += f0.y;
                acc[t][2] += f1.x;
                acc[t][3] += f1.y;
            }
        }
    }

    // Store: lane's output pairs are contiguous -> coalesced STG.64
#pragma unroll
    for (int t = 0; t < 16; ++t) {
        float* orow = out + (size_t)(rowbase + t) * OUTFEAT + o0;
        float2 a; a.x = acc[t][0]; a.y = acc[t][1];
        float2 b; b.x = acc[t][2]; b.y = acc[t][3];
        *reinterpret_cast<float2*>(orow + 2 * lane)      = a;
        *reinterpret_cast<float2*>(orow + 64 + 2 * lane) = b;
    }
}

// ---------------------------------------------------------------------------
// Launch. Inputs: inputMatrix f32, dims i32, selection_matrix (unused),
// thresholds f32, tree_des_mat (unused), lut f32[4096][256][16].
// ---------------------------------------------------------------------------
extern "C" void kernel_launch(void* const* d_in, const int* in_sizes, int n_in,
                              void* d_out, int out_size)
{
    const float* input = (const float*)d_in[0];
    const int*   dims  = (const int*)  d_in[1];
    const float* thr   = (const float*)d_in[3];
    const float* lut   = (const float*)d_in[5];
    float*       out   = (float*)d_out;

    (void)in_sizes; (void)n_in; (void)out_size;

    cudaFuncSetAttribute(agg_kernel,
                         cudaFuncAttributeMaxDynamicSharedMemorySize, AGG_SMEM);

    encode_kernel<<<NROWS, NCODE>>>(input, dims, thr);

    dim3 tgrid(KGLOB / 64, OUTFEAT / 64);
    transpose_kernel<<<tgrid, 256>>>(lut);

    dim3 grid(OUTFEAT / TO, NROWS / TN);
    agg_kernel<<<grid, 256, AGG_SMEM>>>(out);
}